// round 17
// baseline (speedup 1.0000x reference)
#include <cuda_runtime.h>
#include <cuda_bf16.h>

// TopKPool_16372415332892
// out[b] = (1/K) * sum_{topK rows} x[row] * tanh((x[row].w)/||w||)
// B=256, N=512, D=256, K=256. edge_index/batch dead inputs.

#define BB 256
#define NN 512
#define DD 256
#define KK 256

__device__ float g_score[BB * NN];   // raw dot products (selection monotone in this)

// ---------------- Kernel 1: scores (2 rows/warp, wide grid — frozen) ----------------
// grid = B*N/16 = 8192 blocks, 256 threads.
__global__ __launch_bounds__(256)
void score_kernel(const float* __restrict__ x, const float* __restrict__ w)
{
    const int lane = threadIdx.x & 31;
    const int warp = threadIdx.x >> 5;
    const int row0 = blockIdx.x * 16 + warp * 2;

    const float4 wa = *reinterpret_cast<const float4*>(w + lane * 4);
    const float4 wb = *reinterpret_cast<const float4*>(w + 128 + lane * 4);

    const float* r0 = x + (size_t)row0 * DD;
    const float* r1 = r0 + DD;
    const float4 a0 = *reinterpret_cast<const float4*>(r0 + lane * 4);
    const float4 c0 = *reinterpret_cast<const float4*>(r0 + 128 + lane * 4);
    const float4 a1 = *reinterpret_cast<const float4*>(r1 + lane * 4);
    const float4 c1 = *reinterpret_cast<const float4*>(r1 + 128 + lane * 4);

    float d0 = a0.x * wa.x + a0.y * wa.y + a0.z * wa.z + a0.w * wa.w
             + c0.x * wb.x + c0.y * wb.y + c0.z * wb.z + c0.w * wb.w;
    float d1 = a1.x * wa.x + a1.y * wa.y + a1.z * wa.z + a1.w * wa.w
             + c1.x * wb.x + c1.y * wb.y + c1.z * wb.z + c1.w * wb.w;
    #pragma unroll
    for (int o = 16; o; o >>= 1) {
        d0 += __shfl_xor_sync(0xffffffffu, d0, o);
        d1 += __shfl_xor_sync(0xffffffffu, d1, o);
    }
    if (lane == 0) {
        g_score[row0]     = d0;
        g_score[row0 + 1] = d1;
    }
}

// ---------------- Kernel 2: redundant select + column-split gather ----------------
// grid = B*4 blocks, 256 threads. Block = (graph b, column slice c: cols [c*64, c*64+64)).
// Each block INDEPENDENTLY runs the radix top-K select for its graph (bitwise-
// identical across the graph's 4 blocks -> deterministic), then gathers ALL K
// rows for its 64 columns (thread = (col, row-quarter)), folds the 4 quarters
// in smem, and writes out directly. No global partials, no fences, no atomics.
__global__ __launch_bounds__(256)
void select_gather_kernel(const float* __restrict__ x,
                          const float* __restrict__ w,
                          float* __restrict__ out)
{
    __shared__ unsigned hist[256];
    __shared__ unsigned sscan[256];   // sscan[v] = # active nodes with byte >= v
    __shared__ unsigned s_t, s_gt, s_remk;
    __shared__ int s_wA[8], s_wB[8], s_pA[8], s_pB[8];
    __shared__ float s_inv;
    __shared__ int2  s_all[KK];       // full compacted selection for this graph
    __shared__ float s_part[256];

    const int tid  = threadIdx.x;
    const int lane = tid & 31;
    const int warp = tid >> 5;
    const int b    = blockIdx.x >> 2;
    const int c    = blockIdx.x & 3;

    // ---- ||w||^-1 ----
    if (warp == 0) {
        float ssq = 0.f;
        #pragma unroll
        for (int i = 0; i < 8; i++) { float v = w[lane + i * 32]; ssq += v * v; }
        #pragma unroll
        for (int o = 16; o; o >>= 1) ssq += __shfl_xor_sync(0xffffffffu, ssq, o);
        if (lane == 0) s_inv = rsqrtf(ssq);
    }
    if (tid == 0) s_remk = KK;

    // ---- radix top-K select: thread owns nodes tid and tid+256 ----
    const float* sc = g_score + b * NN;
    const float s0v = sc[tid];
    const float s1v = sc[tid + 256];
    const unsigned bits0 = __float_as_uint(s0v);
    const unsigned bits1 = __float_as_uint(s1v);
    const unsigned key0 = (bits0 & 0x80000000u) ? ~bits0 : (bits0 | 0x80000000u);
    const unsigned key1 = (bits1 & 0x80000000u) ? ~bits1 : (bits1 | 0x80000000u);

    bool act0 = true, act1 = true, sel0 = false, sel1 = false;
    bool done = false;

    for (int pass = 0; pass < 4; ++pass) {
        hist[tid] = 0u;
        __syncthreads();
        const unsigned sh = 24 - 8 * pass;
        const unsigned b0 = (key0 >> sh) & 0xFFu;
        const unsigned b1 = (key1 >> sh) & 0xFFu;
        if (act0) atomicAdd(&hist[b0], 1u);
        if (act1) atomicAdd(&hist[b1], 1u);
        __syncthreads();

        // suffix scan of hist by warp 0: lane l owns bins [8l, 8l+8)
        if (warp == 0) {
            unsigned tot = 0;
            #pragma unroll
            for (int j = 0; j < 8; j++) tot += hist[lane * 8 + j];
            unsigned suf = tot;
            #pragma unroll
            for (int o = 1; o < 32; o <<= 1) {
                unsigned t2 = __shfl_down_sync(0xffffffffu, suf, o);
                if (lane + o < 32) suf += t2;
            }
            unsigned run = suf - tot;
            #pragma unroll
            for (int j = 7; j >= 0; --j) {
                run += hist[lane * 8 + j];
                sscan[lane * 8 + j] = run;
            }
        }
        __syncthreads();

        const unsigned remk = s_remk;
        {
            const unsigned ge = sscan[tid];
            const unsigned gt = (tid == 255) ? 0u : sscan[tid + 1];
            if (ge >= remk && gt < remk) { s_t = (unsigned)tid; s_gt = gt; }
        }
        __syncthreads();

        const unsigned t    = s_t;
        const unsigned gt   = s_gt;
        const unsigned eq   = sscan[t] - gt;     // # actives tied at threshold byte
        const unsigned nrem = remk - gt;         // slots left among the tied
        done = (eq == nrem);                     // all tied actives are selected

        if (act0) {
            if (b0 > t)      { sel0 = true; act0 = false; }
            else if (b0 < t) { act0 = false; }
            else if (done)   { sel0 = true; act0 = false; }
        }
        if (act1) {
            if (b1 > t)      { sel1 = true; act1 = false; }
            else if (b1 < t) { act1 = false; }
            else if (done)   { sel1 = true; act1 = false; }
        }
        if (tid == 0) s_remk = nrem;
        __syncthreads();
        if (done) break;   // uniform across block (computed from shared data)
    }

    // ties at the K-th key (only if not resolved): lowest node indices win
    // (jax.lax.top_k tie-break). Set A = nodes [0,256), set B = nodes [256,512).
    if (!done) {
        const unsigned mA = __ballot_sync(0xffffffffu, act0);
        const unsigned mB = __ballot_sync(0xffffffffu, act1);
        if (lane == 0) { s_wA[warp] = __popc(mA); s_wB[warp] = __popc(mB); }
        __syncthreads();
        if (tid == 0) {
            int run = 0;
            #pragma unroll
            for (int i = 0; i < 8; i++) { s_pA[i] = run; run += s_wA[i]; }
            #pragma unroll
            for (int i = 0; i < 8; i++) { s_pB[i] = run; run += s_wB[i]; }
        }
        __syncthreads();
        const unsigned remk = s_remk;
        const unsigned lt = (1u << lane) - 1u;
        if (act0 && (unsigned)(s_pA[warp] + __popc(mA & lt)) < remk) sel0 = true;
        if (act1 && (unsigned)(s_pB[warp] + __popc(mB & lt)) < remk) sel1 = true;
        __syncthreads();
    }

    // deterministic compaction into smem, ordered by node index (A then B)
    {
        const unsigned cA = __ballot_sync(0xffffffffu, sel0);
        const unsigned cB = __ballot_sync(0xffffffffu, sel1);
        if (lane == 0) { s_wA[warp] = __popc(cA); s_wB[warp] = __popc(cB); }
        __syncthreads();
        if (tid == 0) {
            int run = 0;
            #pragma unroll
            for (int i = 0; i < 8; i++) { s_pA[i] = run; run += s_wA[i]; }
            #pragma unroll
            for (int i = 0; i < 8; i++) { s_pB[i] = run; run += s_wB[i]; }
        }
        __syncthreads();
        const float inv = s_inv;
        const unsigned lt = (1u << lane) - 1u;
        if (sel0) {
            const int slot = s_pA[warp] + __popc(cA & lt);
            s_all[slot] = make_int2(tid, __float_as_int(tanhf(s0v * inv)));
        }
        if (sel1) {
            const int slot = s_pB[warp] + __popc(cB & lt);
            s_all[slot] = make_int2(tid + 256, __float_as_int(tanhf(s1v * inv)));
        }
    }
    __syncthreads();

    // ---- gather: thread = (col = tid&63 within slice c, quarter q = tid>>6) ----
    // Thread accumulates rows [q*64, q*64+64) for its column; fold 4 quarters in smem.
    const int col = (tid & 63);
    const int q   = tid >> 6;
    const float* xb = x + (size_t)b * NN * DD + c * 64 + col;

    float a0 = 0.f, a1 = 0.f, a2 = 0.f, a3 = 0.f;
    const int k0 = q * 64;
    #pragma unroll 16
    for (int k = k0; k < k0 + 64; k += 4) {
        const int2 p0 = s_all[k];
        const int2 p1 = s_all[k + 1];
        const int2 p2 = s_all[k + 2];
        const int2 p3 = s_all[k + 3];
        a0 += xb[(size_t)p0.x * DD] * __int_as_float(p0.y);
        a1 += xb[(size_t)p1.x * DD] * __int_as_float(p1.y);
        a2 += xb[(size_t)p2.x * DD] * __int_as_float(p2.y);
        a3 += xb[(size_t)p3.x * DD] * __int_as_float(p3.y);
    }
    s_part[tid] = (a0 + a1) + (a2 + a3);
    __syncthreads();

    if (tid < 64) {
        const float v = (s_part[tid] + s_part[tid + 64])
                      + (s_part[tid + 128] + s_part[tid + 192]);
        out[b * DD + c * 64 + tid] = v * (1.0f / (float)KK);
    }
}

extern "C" void kernel_launch(void* const* d_in, const int* in_sizes, int n_in,
                              void* d_out, int out_size)
{
    (void)in_sizes; (void)n_in; (void)out_size;
    const float* x = (const float*)d_in[0];
    const float* w = (const float*)d_in[1];
    float* out = (float*)d_out;

    score_kernel<<<(BB * NN) / 16, 256>>>(x, w);
    select_gather_kernel<<<BB * 4, 256>>>(x, w, out);
}